// round 9
// baseline (speedup 1.0000x reference)
#include <cuda_runtime.h>
#include <cuda_bf16.h>
#include <math_constants.h>
#include <cstdint>

#define M_PTS 8192
#define C_DIM 64
#define KNN 20
#define NSPLIT 2
#define SPAN (M_PTS / NSPLIT)    // candidates per split (4096)
#define QTILE 128                // queries per block
#define CTILE 64                 // candidates per tile
#define NTILES (SPAN / CTILE)    // 64

#define AS_STRIDE 132            // floats per A row (128 + 4 pad)
#define BS_STRIDE 196            // floats per B row (192 + 4 pad)
#define DS_STRIDE 68             // dist row stride

#define AS_FLOATS (QTILE * AS_STRIDE)          // 16896
#define BS_FLOATS (CTILE * BS_STRIDE)          // 12544
#define SMEM_FLOATS (AS_FLOATS + BS_FLOATS + 64)

// ---------------- scratch (device globals; no allocation allowed) -------------
__device__ float g_sq[M_PTS];
__device__ float g_pd[NSPLIT * M_PTS * KNN];
__device__ int   g_pi[NSPLIT * M_PTS * KNN];
__device__ int   g_knn[M_PTS * KNN];
__device__ float g_gb[M_PTS * C_DIM];   // Wb^T f
__device__ float g_u [M_PTS * C_DIM];   // b1 + Wa^T f - Wb^T f

// ---------------- helpers ------------------------------------------------------
__device__ __forceinline__ float tf32_rna(float x) {
    uint32_t u;
    asm("cvt.rna.tf32.f32 %0, %1;" : "=r"(u) : "f"(x));
    return __uint_as_float(u);
}
__device__ __forceinline__ void mma_tf32(float* c, uint32_t a0, uint32_t a1,
                                         uint32_t a2, uint32_t a3,
                                         uint32_t b0, uint32_t b1) {
    asm volatile(
        "mma.sync.aligned.m16n8k8.row.col.f32.tf32.tf32.f32 "
        "{%0,%1,%2,%3}, {%4,%5,%6,%7}, {%8,%9}, {%0,%1,%2,%3};"
        : "+f"(c[0]), "+f"(c[1]), "+f"(c[2]), "+f"(c[3])
        : "r"(a0), "r"(a1), "r"(a2), "r"(a3), "r"(b0), "r"(b1));
}

// ---------------- kernel 0: squared norms ------------------------------------
__global__ void sq_kernel(const float* __restrict__ pos) {
    int i = blockIdx.x * blockDim.x + threadIdx.x;
    if (i >= M_PTS) return;
    const float4* p4 = reinterpret_cast<const float4*>(pos + i * C_DIM);
    float s = 0.f;
#pragma unroll
    for (int v = 0; v < C_DIM / 4; v++) {
        float4 a = p4[v];
        s += a.x * a.x + a.y * a.y + a.z * a.z + a.w * a.w;
    }
    g_sq[i] = s;
}

// ---------------- kernel 1: tensor-core KNN (legacy mma.sync, split-tf32) -----
__global__ __launch_bounds__(128) void knn_part(const float* __restrict__ pos) {
    extern __shared__ float sm[];
    float* As   = sm;                         // [128][AS_STRIDE]  big|small
    float* Bs   = sm + AS_FLOATS;             // [64][BS_STRIDE]   big|small|big
    float* dist = Bs;                         // [128][DS_STRIDE]  (aliases Bs)
    float* tsq  = sm + AS_FLOATS + BS_FLOATS; // [64]

    const int tid = threadIdx.x;
    const int wid = tid >> 5;
    const int lane = tid & 31;
    const int qbase = blockIdx.x * QTILE;
    const int cand0 = blockIdx.y * SPAN;

    // ---- load A (queries), split into tf32 big / small halves ----
    {
        const float4* p4 = reinterpret_cast<const float4*>(pos + qbase * C_DIM);
#pragma unroll
        for (int i = 0; i < 16; i++) {
            int e4 = tid + i * 128;
            int row = e4 >> 4;
            int c4 = (e4 & 15) * 4;
            float4 v = p4[e4];
            float bx = tf32_rna(v.x), by = tf32_rna(v.y);
            float bz = tf32_rna(v.z), bw = tf32_rna(v.w);
            float4 big = make_float4(bx, by, bz, bw);
            float4 sml = make_float4(tf32_rna(v.x - bx), tf32_rna(v.y - by),
                                     tf32_rna(v.z - bz), tf32_rna(v.w - bw));
            *reinterpret_cast<float4*>(As + row * AS_STRIDE + c4) = big;
            *reinterpret_cast<float4*>(As + row * AS_STRIDE + 64 + c4) = sml;
        }
    }

    const float myq = g_sq[qbase + tid];
    float bd[KNN];
    int bi[KNN];
#pragma unroll
    for (int i = 0; i < KNN; i++) { bd[i] = CUDART_INF_F; bi[i] = -1; }

    for (int t = 0; t < NTILES; t++) {
        const int t0 = cand0 + t * CTILE;
        __syncthreads();   // prev-iter dist reads done; A ready (iter 0)

        // ---- load B tile: [big | small | big] ----
        {
            const float4* b4 = reinterpret_cast<const float4*>(pos + t0 * C_DIM);
#pragma unroll
            for (int i = 0; i < 8; i++) {
                int e4 = tid + i * 128;
                int row = e4 >> 4;
                int c4 = (e4 & 15) * 4;
                float4 v = b4[e4];
                float bx = tf32_rna(v.x), by = tf32_rna(v.y);
                float bz = tf32_rna(v.z), bw = tf32_rna(v.w);
                float4 big = make_float4(bx, by, bz, bw);
                float4 sml = make_float4(tf32_rna(v.x - bx), tf32_rna(v.y - by),
                                         tf32_rna(v.z - bz), tf32_rna(v.w - bw));
                *reinterpret_cast<float4*>(Bs + row * BS_STRIDE + c4) = big;
                *reinterpret_cast<float4*>(Bs + row * BS_STRIDE + 64 + c4) = sml;
                *reinterpret_cast<float4*>(Bs + row * BS_STRIDE + 128 + c4) = big;
            }
            if (tid < CTILE) tsq[tid] = g_sq[t0 + tid];
        }
        __syncthreads();

        // ---- GEMM: 2 m-tiles x 8 n-tiles, 32 K-steps (2 split passes) ----
        float acc[2][8][4];
#pragma unroll
        for (int mt = 0; mt < 2; mt++)
#pragma unroll
            for (int nt = 0; nt < 8; nt++)
#pragma unroll
                for (int r = 0; r < 4; r++) acc[mt][nt][r] = 0.f;

#pragma unroll 4
        for (int s = 0; s < 32; s++) {
            int akc = (s & 15) * 8;
            int bkc = (s < 16) ? akc : akc + 64;
            uint32_t af[2][4];
#pragma unroll
            for (int mt = 0; mt < 2; mt++) {
                const float* ap = As + (wid * 32 + mt * 16 + (lane >> 2)) * AS_STRIDE
                                  + akc + (lane & 3);
                af[mt][0] = __float_as_uint(ap[0]);
                af[mt][1] = __float_as_uint(ap[8 * AS_STRIDE]);
                af[mt][2] = __float_as_uint(ap[4]);
                af[mt][3] = __float_as_uint(ap[8 * AS_STRIDE + 4]);
            }
#pragma unroll
            for (int nt = 0; nt < 8; nt++) {
                const float* bp = Bs + (nt * 8 + (lane >> 2)) * BS_STRIDE
                                  + bkc + (lane & 3);
                uint32_t b0 = __float_as_uint(bp[0]);
                uint32_t b1 = __float_as_uint(bp[4]);
                mma_tf32(acc[0][nt], af[0][0], af[0][1], af[0][2], af[0][3], b0, b1);
                mma_tf32(acc[1][nt], af[1][0], af[1][1], af[1][2], af[1][3], b0, b1);
            }
        }
        __syncthreads();   // all warps done reading Bs before dist overwrite

        // ---- scatter dots to dist buffer ----
#pragma unroll
        for (int mt = 0; mt < 2; mt++) {
            int r0 = wid * 32 + mt * 16 + (lane >> 2);
#pragma unroll
            for (int nt = 0; nt < 8; nt++) {
                int col = nt * 8 + 2 * (lane & 3);
                *reinterpret_cast<float2*>(dist + r0 * DS_STRIDE + col) =
                    make_float2(acc[mt][nt][0], acc[mt][nt][1]);
                *reinterpret_cast<float2*>(dist + (r0 + 8) * DS_STRIDE + col) =
                    make_float2(acc[mt][nt][2], acc[mt][nt][3]);
            }
        }
        __syncthreads();

        // ---- epilogue: thread == query row, ascending candidate order ----
        {
            const float4* dr = reinterpret_cast<const float4*>(dist + tid * DS_STRIDE);
            const float4* tq = reinterpret_cast<const float4*>(tsq);
#pragma unroll
            for (int g = 0; g < 16; g++) {
                float4 dv = dr[g];
                float4 tv = tq[g];
                float dc[4];
                dc[0] = fmaf(-2.0f, dv.x, myq + tv.x);
                dc[1] = fmaf(-2.0f, dv.y, myq + tv.y);
                dc[2] = fmaf(-2.0f, dv.z, myq + tv.z);
                dc[3] = fmaf(-2.0f, dv.w, myq + tv.w);
#pragma unroll
                for (int u = 0; u < 4; u++) {
                    if (dc[u] < bd[KNN - 1]) {
                        float cd = dc[u];
                        int ci = t0 + g * 4 + u;
#pragma unroll
                        for (int i = 0; i < KNN; i++) {
                            bool sw = cd < bd[i];
                            float tf = bd[i]; int ti = bi[i];
                            bd[i] = sw ? cd : bd[i];
                            bi[i] = sw ? ci : bi[i];
                            cd = sw ? tf : cd;
                            ci = sw ? ti : ci;
                        }
                    }
                }
            }
        }
    }

    const int base = (blockIdx.y * M_PTS + qbase + tid) * KNN;
#pragma unroll
    for (int i = 0; i < KNN; i++) { g_pd[base + i] = bd[i]; g_pi[base + i] = bi[i]; }
}

// ---------------- kernel 2: merge the partial (sorted) lists ------------------
__global__ __launch_bounds__(128) void knn_merge() {
    int q = blockIdx.x * blockDim.x + threadIdx.x;
    if (q >= M_PTS) return;
    float d[NSPLIT * KNN];
    int id[NSPLIT * KNN];
#pragma unroll
    for (int h = 0; h < NSPLIT; h++)
#pragma unroll
        for (int i = 0; i < KNN; i++) {
            d[h * KNN + i] = g_pd[(h * M_PTS + q) * KNN + i];
            id[h * KNN + i] = g_pi[(h * M_PTS + q) * KNN + i];
        }
    int hp[NSPLIT];
#pragma unroll
    for (int h = 0; h < NSPLIT; h++) hp[h] = 0;
    for (int s = 0; s < KNN; s++) {
        float bm = CUDART_INF_F; int bh = 0; int bid_ = 0x7fffffff;
#pragma unroll
        for (int h = 0; h < NSPLIT; h++) {
            float dv = d[h * KNN + hp[h]];
            int iv = id[h * KNN + hp[h]];
            if (dv < bm || (dv == bm && iv < bid_)) { bm = dv; bh = h; bid_ = iv; }
        }
        g_knn[q * KNN + s] = bid_;
        hp[bh]++;
    }
}

// ---------------- kernel 3: precompute u[p], g[p] -----------------------------
// h_k(q) = relu(u[q] + g[nbr_k]),  g[p] = Wb^T f_p,  u[q] = b1 + Wa^T f_q - g[q]
__global__ __launch_bounds__(256) void pre_kernel(
    const float* __restrict__ f,
    const float* __restrict__ W1, const float* __restrict__ b1)
{
    __shared__ float W1s[128 * 64];
    __shared__ float fs[32 * 64];
    const int tid = threadIdx.x;
    for (int i = tid; i < 128 * 64; i += 256) W1s[i] = W1[i];
    const int p0 = blockIdx.x * 32;
    for (int i = tid; i < 32 * 64; i += 256) fs[i] = f[p0 * 64 + i];
    __syncthreads();

    const int o = tid & 63;
    const int sub = tid >> 6;
    const float bb1 = b1[o];
    for (int pi = sub; pi < 32; pi += 4) {
        float u = bb1, g = 0.f;
#pragma unroll
        for (int c = 0; c < 64; c++) {
            float fv = fs[pi * 64 + c];
            u = fmaf(fv, W1s[c * 64 + o], u);
            g = fmaf(fv, W1s[(64 + c) * 64 + o], g);
        }
        g_gb[(p0 + pi) * 64 + o] = g;
        g_u [(p0 + pi) * 64 + o] = u - g;
    }
}

// ---------------- kernel 4: layer2 + max aggregation --------------------------
__global__ __launch_bounds__(128) void mlp_kernel(
    const float* __restrict__ W2, const float* __restrict__ b2,
    float* __restrict__ out)
{
    __shared__ float W2s[64 * 64];
    __shared__ float hs[2][KNN * 64];
    __shared__ int sidx[2][KNN];

    const int tid = threadIdx.x;
    const int sub = tid >> 6;
    const int o = tid & 63;
    const int q = blockIdx.x * 2 + sub;

    for (int i = tid; i < 64 * 64; i += 128) W2s[i] = W2[i];
    if (o < KNN) sidx[sub][o] = g_knn[q * KNN + o];
    __syncthreads();

    const float u = g_u[q * 64 + o];
#pragma unroll
    for (int k = 0; k < KNN; k++) {
        int nb = sidx[sub][k];
        hs[sub][k * 64 + o] = fmaxf(u + g_gb[nb * 64 + o], 0.f);
    }
    __syncthreads();

    float acc[KNN];
#pragma unroll
    for (int k = 0; k < KNN; k++) acc[k] = 0.f;
#pragma unroll
    for (int c = 0; c < 64; c++) {
        float w = W2s[c * 64 + o];
#pragma unroll
        for (int k = 0; k < KNN; k++)
            acc[k] = fmaf(hs[sub][k * 64 + c], w, acc[k]);
    }
    float v = acc[0];
#pragma unroll
    for (int k = 1; k < KNN; k++) v = fmaxf(v, acc[k]);
    out[q * 64 + o] = v + b2[o];
}

// ---------------- launch -------------------------------------------------------
extern "C" void kernel_launch(void* const* d_in, const int* in_sizes, int n_in,
                              void* d_out, int out_size)
{
    const float* pos  = (const float*)d_in[0];
    const float* feat = (const float*)d_in[1];
    const float* W1   = (const float*)d_in[2];
    const float* b1   = (const float*)d_in[3];
    const float* W2   = (const float*)d_in[4];
    const float* b2   = (const float*)d_in[5];
    float* out = (float*)d_out;

    sq_kernel<<<(M_PTS + 255) / 256, 256>>>(pos);

    const int smem_bytes = SMEM_FLOATS * (int)sizeof(float);
    cudaFuncSetAttribute(knn_part, cudaFuncAttributeMaxDynamicSharedMemorySize,
                         smem_bytes);
    dim3 kg(M_PTS / QTILE, NSPLIT);
    knn_part<<<kg, 128, smem_bytes>>>(pos);

    knn_merge<<<(M_PTS + 127) / 128, 128>>>();

    pre_kernel<<<M_PTS / 32, 256>>>(feat, W1, b1);

    mlp_kernel<<<M_PTS / 2, 128>>>(W2, b2, out);
}

// round 12
// speedup vs baseline: 2.5404x; 2.5404x over previous
#include <cuda_runtime.h>
#include <cuda_bf16.h>
#include <math_constants.h>
#include <cstdint>

#define M_PTS 8192
#define C_DIM 64
#define KNN 20
#define NSPLIT 4
#define SPAN (M_PTS / NSPLIT)   // candidates per split (2048)
#define QB 128                  // queries (=threads) per knn block
#define CT 128                  // candidate tile
#define CHUNK 32                // candidates between cleanups (== surv capacity)

typedef unsigned long long ull;

// ---------------- scratch (device globals; no allocation allowed) -------------
__device__ float g_sq[M_PTS];
__device__ float g_pd[NSPLIT * M_PTS * KNN];
__device__ int   g_pi[NSPLIT * M_PTS * KNN];
__device__ int   g_knn[M_PTS * KNN];
__device__ float g_gb[M_PTS * C_DIM];   // Wb^T f
__device__ float g_u [M_PTS * C_DIM];   // b1 + Wa^T f - Wb^T f

// ---------------- f32x2 helpers ----------------------------------------------
__device__ __forceinline__ ull ffma2(ull a, ull b, ull c) {
    ull d;
    asm("fma.rn.f32x2 %0, %1, %2, %3;" : "=l"(d) : "l"(a), "l"(b), "l"(c));
    return d;
}
__device__ __forceinline__ ull addf2(ull a, ull b) {
    ull d;
    asm("add.rn.f32x2 %0, %1, %2;" : "=l"(d) : "l"(a), "l"(b));
    return d;
}
__device__ __forceinline__ ull pack2(float x, float y) {
    ull r;
    asm("mov.b64 %0, {%1, %2};" : "=l"(r) : "f"(x), "f"(y));
    return r;
}
__device__ __forceinline__ void unpack2(ull v, float& lo, float& hi) {
    asm("mov.b64 {%0, %1}, %2;" : "=f"(lo), "=f"(hi) : "l"(v));
}

// ---------------- kernel 0: squared norms ------------------------------------
__global__ void sq_kernel(const float* __restrict__ pos) {
    int i = blockIdx.x * blockDim.x + threadIdx.x;
    if (i >= M_PTS) return;
    const float4* p4 = reinterpret_cast<const float4*>(pos + i * C_DIM);
    float s = 0.f;
#pragma unroll
    for (int v = 0; v < C_DIM / 4; v++) {
        float4 a = p4[v];
        s += a.x * a.x + a.y * a.y + a.z * a.z + a.w * a.w;
    }
    g_sq[i] = s;
}

// ---------------- kernel 1: partial KNN with batched inserts ------------------
// smem layout (dynamic): tile float4[CT*16] | tsq[CT] | sd[CHUNK*QB] | si[CHUNK*QB]
#define SMEM_KNN_BYTES (CT * 64 * 4 + CT * 4 + CHUNK * QB * 4 + CHUNK * QB * 4)
__global__ __launch_bounds__(QB) void knn_part(const float* __restrict__ pos) {
    extern __shared__ char dyn[];
    float4* tile = reinterpret_cast<float4*>(dyn);
    float*  tsq  = reinterpret_cast<float*>(dyn + CT * 64 * 4);
    float*  sd   = reinterpret_cast<float*>(dyn + CT * 64 * 4 + CT * 4);
    int*    si   = reinterpret_cast<int*>(dyn + CT * 64 * 4 + CT * 4 + CHUNK * QB * 4);

    const int tid = threadIdx.x;
    const int q = blockIdx.x * QB + tid;
    const int split = blockIdx.y;
    const int cand0 = split * SPAN;
    const int cand1 = cand0 + SPAN;

    const float4* pos4 = reinterpret_cast<const float4*>(pos);

    // query packed as 32 x f32x2
    ull q2[C_DIM / 2];
#pragma unroll
    for (int v = 0; v < C_DIM / 4; v++) {
        float4 a = pos4[q * (C_DIM / 4) + v];
        q2[2 * v]     = pack2(a.x, a.y);
        q2[2 * v + 1] = pack2(a.z, a.w);
    }
    const float myq = g_sq[q];

    // sorted ascending; bd[KNN-1] = current worst kept (prune threshold)
    float bd[KNN];
    int bi[KNN];
#pragma unroll
    for (int i = 0; i < KNN; i++) { bd[i] = CUDART_INF_F; bi[i] = -1; }

    int cnt = 0;

    for (int t0 = cand0; t0 < cand1; t0 += CT) {
        __syncthreads();
#pragma unroll
        for (int i = 0; i < (CT * (C_DIM / 4)) / QB; i++) {
            int fl = i * QB + tid;
            tile[fl] = pos4[t0 * (C_DIM / 4) + fl];
        }
        tsq[tid] = g_sq[t0 + tid];   // QB == CT
        __syncthreads();

        const ulonglong2* tl = reinterpret_cast<const ulonglong2*>(tile);

        for (int c0 = 0; c0 < CT; c0 += CHUNK) {
            // ---- compute + branchless push over one chunk ----
            for (int j = c0; j < c0 + CHUNK; j += 4) {
                ull a00 = 0, a01 = 0, a10 = 0, a11 = 0;
                ull a20 = 0, a21 = 0, a30 = 0, a31 = 0;
#pragma unroll
                for (int v = 0; v < 16; v++) {
                    ulonglong2 cA = tl[(j + 0) * 16 + v];
                    ulonglong2 cB = tl[(j + 1) * 16 + v];
                    ulonglong2 cC = tl[(j + 2) * 16 + v];
                    ulonglong2 cD = tl[(j + 3) * 16 + v];
                    ull qa = q2[2 * v], qb = q2[2 * v + 1];
                    a00 = ffma2(qa, cA.x, a00);  a01 = ffma2(qb, cA.y, a01);
                    a10 = ffma2(qa, cB.x, a10);  a11 = ffma2(qb, cB.y, a11);
                    a20 = ffma2(qa, cC.x, a20);  a21 = ffma2(qb, cC.y, a21);
                    a30 = ffma2(qa, cD.x, a30);  a31 = ffma2(qb, cD.y, a31);
                }
                float dsc[4];
                {
                    float lo, hi;
                    ull s0 = addf2(a00, a01); unpack2(s0, lo, hi);
                    dsc[0] = fmaf(-2.0f, lo + hi, myq + tsq[j + 0]);
                    ull s1 = addf2(a10, a11); unpack2(s1, lo, hi);
                    dsc[1] = fmaf(-2.0f, lo + hi, myq + tsq[j + 1]);
                    ull s2 = addf2(a20, a21); unpack2(s2, lo, hi);
                    dsc[2] = fmaf(-2.0f, lo + hi, myq + tsq[j + 2]);
                    ull s3 = addf2(a30, a31); unpack2(s3, lo, hi);
                    dsc[3] = fmaf(-2.0f, lo + hi, myq + tsq[j + 3]);
                }
                // branchless push: always store to slot cnt, bump cnt on pass.
                // garbage stores beyond final cnt are never read.
#pragma unroll
                for (int u = 0; u < 4; u++) {
                    sd[cnt * QB + tid] = dsc[u];
                    si[cnt * QB + tid] = t0 + j + u;
                    cnt += (dsc[u] < bd[KNN - 1]) ? 1 : 0;
                }
            }

            // ---- batched cleanup: warp-max iterations of the swap chain ----
            int mx = __reduce_max_sync(0xffffffffu, cnt);
            for (int i = 0; i < mx; i++) {
                bool act = (i < cnt);
                float cd0 = sd[i * QB + tid];
                int ci0 = si[i * QB + tid];
                float cd = act ? cd0 : CUDART_INF_F;
                int ci = act ? ci0 : -1;
                if (cd < bd[KNN - 1]) {
#pragma unroll
                    for (int k = 0; k < KNN; k++) {
                        bool sw = cd < bd[k];
                        float tf = bd[k]; int ti = bi[k];
                        bd[k] = sw ? cd : bd[k];
                        bi[k] = sw ? ci : bi[k];
                        cd = sw ? tf : cd;
                        ci = sw ? ti : ci;
                    }
                }
            }
            cnt = 0;
        }
    }

    const int base = (split * M_PTS + q) * KNN;
#pragma unroll
    for (int i = 0; i < KNN; i++) { g_pd[base + i] = bd[i]; g_pi[base + i] = bi[i]; }
}

// ---------------- kernel 2: merge the partial (sorted) lists ------------------
__global__ __launch_bounds__(128) void knn_merge() {
    int q = blockIdx.x * blockDim.x + threadIdx.x;
    if (q >= M_PTS) return;
    float d[NSPLIT * KNN];
    int id[NSPLIT * KNN];
#pragma unroll
    for (int h = 0; h < NSPLIT; h++)
#pragma unroll
        for (int i = 0; i < KNN; i++) {
            d[h * KNN + i] = g_pd[(h * M_PTS + q) * KNN + i];
            id[h * KNN + i] = g_pi[(h * M_PTS + q) * KNN + i];
        }
    int hp[NSPLIT];
#pragma unroll
    for (int h = 0; h < NSPLIT; h++) hp[h] = 0;
    for (int s = 0; s < KNN; s++) {
        float bm = CUDART_INF_F; int bh = 0; int bid_ = 0x7fffffff;
#pragma unroll
        for (int h = 0; h < NSPLIT; h++) {
            float dv = d[h * KNN + hp[h]];
            int iv = id[h * KNN + hp[h]];
            if (dv < bm || (dv == bm && iv < bid_)) { bm = dv; bh = h; bid_ = iv; }
        }
        g_knn[q * KNN + s] = bid_;
        hp[bh]++;
    }
}

// ---------------- kernel 3: precompute u[p], g[p] -----------------------------
// h_k(q) = relu(u[q] + g[nbr_k]),  g[p] = Wb^T f_p,  u[q] = b1 + Wa^T f_q - g[q]
__global__ __launch_bounds__(256) void pre_kernel(
    const float* __restrict__ f,
    const float* __restrict__ W1, const float* __restrict__ b1)
{
    __shared__ float W1s[128 * 64];
    __shared__ float fs[32 * 64];
    const int tid = threadIdx.x;
    for (int i = tid; i < 128 * 64; i += 256) W1s[i] = W1[i];
    const int p0 = blockIdx.x * 32;
    for (int i = tid; i < 32 * 64; i += 256) fs[i] = f[p0 * 64 + i];
    __syncthreads();

    const int o = tid & 63;
    const int sub = tid >> 6;
    const float bb1 = b1[o];
    for (int pi = sub; pi < 32; pi += 4) {
        float u = bb1, g = 0.f;
#pragma unroll
        for (int c = 0; c < 64; c++) {
            float fv = fs[pi * 64 + c];
            u = fmaf(fv, W1s[c * 64 + o], u);
            g = fmaf(fv, W1s[(64 + c) * 64 + o], g);
        }
        g_gb[(p0 + pi) * 64 + o] = g;
        g_u [(p0 + pi) * 64 + o] = u - g;
    }
}

// ---------------- kernel 4: layer2 + max aggregation --------------------------
__global__ __launch_bounds__(128) void mlp_kernel(
    const float* __restrict__ W2, const float* __restrict__ b2,
    float* __restrict__ out)
{
    __shared__ float W2s[64 * 64];
    __shared__ float hs[2][KNN * 64];
    __shared__ int sidx[2][KNN];

    const int tid = threadIdx.x;
    const int sub = tid >> 6;
    const int o = tid & 63;
    const int q = blockIdx.x * 2 + sub;

    for (int i = tid; i < 64 * 64; i += 128) W2s[i] = W2[i];
    if (o < KNN) sidx[sub][o] = g_knn[q * KNN + o];
    __syncthreads();

    const float u = g_u[q * 64 + o];
#pragma unroll
    for (int k = 0; k < KNN; k++) {
        int nb = sidx[sub][k];
        hs[sub][k * 64 + o] = fmaxf(u + g_gb[nb * 64 + o], 0.f);
    }
    __syncthreads();

    float acc[KNN];
#pragma unroll
    for (int k = 0; k < KNN; k++) acc[k] = 0.f;
#pragma unroll
    for (int c = 0; c < 64; c++) {
        float w = W2s[c * 64 + o];
#pragma unroll
        for (int k = 0; k < KNN; k++)
            acc[k] = fmaf(hs[sub][k * 64 + c], w, acc[k]);
    }
    float v = acc[0];
#pragma unroll
    for (int k = 1; k < KNN; k++) v = fmaxf(v, acc[k]);
    out[q * 64 + o] = v + b2[o];
}

// ---------------- launch -------------------------------------------------------
extern "C" void kernel_launch(void* const* d_in, const int* in_sizes, int n_in,
                              void* d_out, int out_size)
{
    const float* pos  = (const float*)d_in[0];
    const float* feat = (const float*)d_in[1];
    const float* W1   = (const float*)d_in[2];
    const float* b1   = (const float*)d_in[3];
    const float* W2   = (const float*)d_in[4];
    const float* b2   = (const float*)d_in[5];
    float* out = (float*)d_out;

    sq_kernel<<<(M_PTS + 255) / 256, 256>>>(pos);

    cudaFuncSetAttribute(knn_part, cudaFuncAttributeMaxDynamicSharedMemorySize,
                         SMEM_KNN_BYTES);
    dim3 kg(M_PTS / QB, NSPLIT);
    knn_part<<<kg, QB, SMEM_KNN_BYTES>>>(pos);

    knn_merge<<<(M_PTS + 127) / 128, 128>>>();

    pre_kernel<<<M_PTS / 32, 256>>>(feat, W1, b1);

    mlp_kernel<<<M_PTS / 2, 128>>>(W2, b2, out);
}